// round 4
// baseline (speedup 1.0000x reference)
#include <cuda_runtime.h>
#include <math.h>

#define Bdim 32
#define Ndim 128
#define Hdim 8
#define Edim 64
#define Cdim 16
#define Ddim 512   // H*E
#define CAP 32     // max stored neighbors per (h,n); actual expected <= 7
#define KSTRIDE 72 // padded floats per smem tile row (breaks bank aliasing)

__device__ unsigned char g_jidx[Hdim * Ndim * CAP];
__device__ int g_jcnt[Hdim * Ndim];
__device__ float g_gate[Bdim * Cdim];

// ---------------------------------------------------------------------------
// Prepass: compact the boolean neighborhood mask into per-(h,n) j-lists.
// Autodetects element width: 1-byte bool vs 4-byte (int32 / float32 — for
// both, "nonzero bits" == true). Detection: mask[h,n,n] is always true.
// ---------------------------------------------------------------------------
__global__ void prep_kernel(const unsigned char* __restrict__ mask) {
    int h = blockIdx.x;
    int n = threadIdx.x;
    __shared__ int ok8;
    if (n == 0) ok8 = 1;
    __syncthreads();
    // 1-byte interpretation diagonal test
    if (mask[(size_t)(h * Ndim + n) * Ndim + n] == 0) atomicExch(&ok8, 0);
    __syncthreads();

    int cnt = 0;
    if (ok8) {
        const unsigned char* row = mask + (size_t)(h * Ndim + n) * Ndim;
        for (int j = 0; j < Ndim; j++) {
            if (row[j] != 0) {
                if (cnt < CAP) g_jidx[(h * Ndim + n) * CAP + cnt] = (unsigned char)j;
                cnt++;
            }
        }
    } else {
        // 4-byte elements: true <=> nonzero bit pattern (works for i32 and f32)
        const unsigned int* m32 = (const unsigned int*)mask;
        const unsigned int* row = m32 + (size_t)(h * Ndim + n) * Ndim;
        for (int j = 0; j < Ndim; j++) {
            if (row[j] != 0u) {
                if (cnt < CAP) g_jidx[(h * Ndim + n) * CAP + cnt] = (unsigned char)j;
                cnt++;
            }
        }
    }
    g_jcnt[h * Ndim + n] = cnt < CAP ? cnt : CAP;
}

// ---------------------------------------------------------------------------
// Gate: v_pool = mean_n values[b,c,n,:,:] -> [D]; gelu(v_pool@w1+b1)@w2+b2
// -> sigmoid. One CTA of 512 threads per (b,c).
// ---------------------------------------------------------------------------
__global__ void gate_kernel(const float* __restrict__ values,
                            const float* __restrict__ w1,
                            const float* __restrict__ b1,
                            const float* __restrict__ w2,
                            const float* __restrict__ b2) {
    int bc = blockIdx.x;      // b*C + c
    int tid = threadIdx.x;    // 0..511
    __shared__ float vp[Ddim];
    __shared__ float hp[512];

    // mean pool over n (coalesced: 512 consecutive floats per n)
    float s = 0.f;
    const float* base = values + (size_t)bc * Ndim * Ddim + tid;
    #pragma unroll 4
    for (int nn = 0; nn < Ndim; nn++) s += base[(size_t)nn * Ddim];
    vp[tid] = s * (1.f / (float)Ndim);
    __syncthreads();

    // hidden: 128 outputs, 4 threads per output (split over d-quarters)
    int k = tid & 127;
    int sub = tid >> 7;
    float hs = 0.f;
    const float* w1p = w1 + k;   // w1 is [D, 128] row-major
    #pragma unroll 4
    for (int dd = 0; dd < 128; dd++) {
        int d = sub * 128 + dd;
        hs = fmaf(vp[d], w1p[d * 128], hs);
    }
    hp[tid] = hs;
    __syncthreads();

    if (tid < 128) {
        float x = hp[tid] + hp[tid + 128] + hp[tid + 256] + hp[tid + 384] + b1[tid];
        // exact gelu: 0.5*x*(1+erf(x/sqrt(2)))
        float g = 0.5f * x * (1.f + erff(x * 0.7071067811865476f));
        hp[tid] = g * w2[tid];
    }
    __syncthreads();
    if (tid < 32) {
        float r = hp[tid] + hp[tid + 32] + hp[tid + 64] + hp[tid + 96];
        #pragma unroll
        for (int o = 16; o; o >>= 1) r += __shfl_xor_sync(0xffffffffu, r, o);
        if (tid == 0) g_gate[bc] = 1.f / (1.f + __expf(-(r + b2[0])));
    }
}

// ---------------------------------------------------------------------------
// Sparse neighborhood attention. CTA per (b,h); 256 threads = 128 rows x 2
// E-halves. Streams c = 0..15 K/V tiles through smem with online softmax.
// ---------------------------------------------------------------------------
__global__ __launch_bounds__(256, 2) void attn_kernel(
        const float* __restrict__ q,
        const float* __restrict__ keys,
        const float* __restrict__ values,
        float* __restrict__ out) {
    extern __shared__ float sm[];
    float* ks = sm;                         // [128][KSTRIDE]
    float* vs = sm + Ndim * KSTRIDE;        // [128][KSTRIDE]
    unsigned char* jl = (unsigned char*)(sm + 2 * Ndim * KSTRIDE); // [128][CAP]
    __shared__ int jc[Ndim];

    const int b = blockIdx.x >> 3;
    const int h = blockIdx.x & 7;
    const int tid = threadIdx.x;
    const int n = tid >> 1;
    const int half = tid & 1;
    const unsigned pm = 0x3u << (tid & 30);  // pair mask within warp

    // stage j-lists
    if (tid < Ndim) jc[tid] = g_jcnt[h * Ndim + tid];
    for (int i = tid; i < Ndim * CAP; i += 256) jl[i] = g_jidx[h * Ndim * CAP + i];

    // load this row's query half into registers
    float4 q4[8];
    {
        const float4* qp = (const float4*)(q + (((size_t)b * Ndim + n) * Hdim + h) * Edim + half * 32);
        #pragma unroll
        for (int t = 0; t < 8; t++) q4[t] = qp[t];
    }

    float4 acc[8];
    #pragma unroll
    for (int t = 0; t < 8; t++) acc[t] = make_float4(0.f, 0.f, 0.f, 0.f);
    float mrun = -INFINITY;
    float lrun = 0.f;

    const int rowstride4 = Hdim * Edim / 4;  // float4 stride between j rows in gmem

    for (int c = 0; c < Cdim; c++) {
        if (c) __syncthreads();   // previous tile fully consumed
        const float4* kb = (const float4*)keys   + (size_t)(b * Cdim + c) * Ndim * rowstride4 + h * (Edim / 4);
        const float4* vb = (const float4*)values + (size_t)(b * Cdim + c) * Ndim * rowstride4 + h * (Edim / 4);
        #pragma unroll 4
        for (int r = tid; r < Ndim * 16; r += 256) {
            int row = r >> 4;
            int sg = r & 15;
            float4 kv = kb[row * rowstride4 + sg];
            float4 vv = vb[row * rowstride4 + sg];
            int off = row * KSTRIDE + (sg >> 3) * 36 + (sg & 7) * 4;
            *(float4*)(ks + off) = kv;
            *(float4*)(vs + off) = vv;
        }
        __syncthreads();

        const float gc = g_gate[b * Cdim + c];
        const int cnt = jc[n];

        for (int basei = 0; basei < cnt; basei += 8) {
            const int nch = min(8, cnt - basei);
            float lg[8];
            int js[8];
            float tmax = -INFINITY;
            for (int i = 0; i < nch; i++) {
                int j = jl[n * CAP + basei + i];
                js[i] = j;
                const float4* kk = (const float4*)(ks + j * KSTRIDE + half * 36);
                float d = 0.f;
                #pragma unroll
                for (int t = 0; t < 8; t++) {
                    float4 kv = kk[t];
                    d = fmaf(q4[t].x, kv.x, d);
                    d = fmaf(q4[t].y, kv.y, d);
                    d = fmaf(q4[t].z, kv.z, d);
                    d = fmaf(q4[t].w, kv.w, d);
                }
                d += __shfl_xor_sync(pm, d, 1);   // combine the two E-halves
                lg[i] = d * 0.125f;               // scale = E^-0.5
                tmax = fmaxf(tmax, lg[i]);
            }
            float mnew = fmaxf(mrun, tmax);
            if (mnew > mrun) {
                float so = __expf(mrun - mnew);   // exp(-inf)=0 on first chunk
                lrun *= so;
                #pragma unroll
                for (int t = 0; t < 8; t++) {
                    acc[t].x *= so; acc[t].y *= so; acc[t].z *= so; acc[t].w *= so;
                }
                mrun = mnew;
            }
            for (int i = 0; i < nch; i++) {
                float p = __expf(lg[i] - mrun);
                lrun += p;                         // denominator excludes gate
                float pg = p * gc;                 // gate folded into V accumulate
                const float4* vv4 = (const float4*)(vs + js[i] * KSTRIDE + half * 36);
                #pragma unroll
                for (int t = 0; t < 8; t++) {
                    float4 vv = vv4[t];
                    acc[t].x = fmaf(pg, vv.x, acc[t].x);
                    acc[t].y = fmaf(pg, vv.y, acc[t].y);
                    acc[t].z = fmaf(pg, vv.z, acc[t].z);
                    acc[t].w = fmaf(pg, vv.w, acc[t].w);
                }
            }
        }
    }

    // lrun > 0 whenever the row has >=1 neighbor (diagonal always valid).
    // Guard anyway so a masked-out row yields 0, never NaN.
    const float inv = (lrun > 0.f) ? (1.f / lrun) : 0.f;
    float4* op = (float4*)(out + (((size_t)b * Ndim + n) * Hdim + h) * Edim + half * 32);
    #pragma unroll
    for (int t = 0; t < 8; t++) {
        float4 a = acc[t];
        a.x *= inv; a.y *= inv; a.z *= inv; a.w *= inv;
        op[t] = a;
    }
}

// ---------------------------------------------------------------------------
extern "C" void kernel_launch(void* const* d_in, const int* in_sizes, int n_in,
                              void* d_out, int out_size) {
    // Resolve inputs by element count (unique up to the two documented pairs),
    // falling back to metadata order.
    int qi = 0, ki = 1, vi = 2, w1i = 3, b1i = 4, w2i = 5, b2i = 6, mi = 7;
    {
        int q = -1, k1st = -1, k2nd = -1, w1x = -1, p1st = -1, p2nd = -1, bx = -1, mx = -1;
        for (int i = 0; i < n_in; i++) {
            int s = in_sizes[i];
            if (s == Bdim * Ndim * Hdim * Edim) q = i;                 // 2097152
            else if (s == Bdim * Cdim * Ndim * Hdim * Edim) {          // 33554432
                if (k1st < 0) k1st = i; else k2nd = i;
            }
            else if (s == Ddim * (Ddim / 4)) w1x = i;                  // 65536
            else if (s == Ddim / 4) { if (p1st < 0) p1st = i; else p2nd = i; } // 128
            else if (s == 1) bx = i;
            else if (s == Hdim * Ndim * Ndim) mx = i;                  // 131072
        }
        if (q >= 0 && k1st >= 0 && k2nd >= 0 && w1x >= 0 && p1st >= 0 &&
            p2nd >= 0 && bx >= 0 && mx >= 0) {
            qi = q; ki = k1st; vi = k2nd; w1i = w1x; b1i = p1st; w2i = p2nd;
            b2i = bx; mi = mx;
        }
    }

    const float* queries = (const float*)d_in[qi];
    const float* keys    = (const float*)d_in[ki];
    const float* values  = (const float*)d_in[vi];
    const float* w1      = (const float*)d_in[w1i];
    const float* b1      = (const float*)d_in[b1i];
    const float* w2      = (const float*)d_in[w2i];
    const float* b2      = (const float*)d_in[b2i];
    const unsigned char* na_mask = (const unsigned char*)d_in[mi];
    float* out = (float*)d_out;

    const int smem_bytes = 2 * Ndim * KSTRIDE * 4 + Ndim * CAP;  // 77824
    cudaFuncSetAttribute(attn_kernel, cudaFuncAttributeMaxDynamicSharedMemorySize, smem_bytes);

    prep_kernel<<<Hdim, Ndim>>>(na_mask);
    gate_kernel<<<Bdim * Cdim, 512>>>(values, w1, b1, w2, b2);
    attn_kernel<<<Bdim * Hdim, 256, smem_bytes>>>(queries, keys, values, out);
}

// round 7
// speedup vs baseline: 1.2451x; 1.2451x over previous
#include <cuda_runtime.h>
#include <math.h>

#define Bdim 32
#define Ndim 128
#define Hdim 8
#define Edim 64
#define Cdim 16
#define Ddim 512   // H*E
#define CAP 128    // max neighbors per row (full safety; actual <= ~7)

__device__ float g_gate[Bdim * Cdim];

// ---------------------------------------------------------------------------
// Gate: v_pool = mean_n values[b,c,n,:,:] -> [D]; gelu(v_pool@w1+b1)@w2+b2
// -> sigmoid. One CTA of 512 threads per (b,c).
// ---------------------------------------------------------------------------
__global__ void gate_kernel(const float* __restrict__ values,
                            const float* __restrict__ w1,
                            const float* __restrict__ b1,
                            const float* __restrict__ w2,
                            const float* __restrict__ b2) {
    int bc = blockIdx.x;      // b*C + c
    int tid = threadIdx.x;    // 0..511
    __shared__ float vp[Ddim];
    __shared__ float hp[512];

    float s = 0.f;
    const float* base = values + (size_t)bc * Ndim * Ddim + tid;
    #pragma unroll 4
    for (int nn = 0; nn < Ndim; nn++) s += base[(size_t)nn * Ddim];
    vp[tid] = s * (1.f / (float)Ndim);
    __syncthreads();

    int k = tid & 127;
    int sub = tid >> 7;
    float hs = 0.f;
    const float* w1p = w1 + k;   // w1 is [D, 128] row-major
    #pragma unroll 4
    for (int dd = 0; dd < 128; dd++) {
        int d = sub * 128 + dd;
        hs = fmaf(vp[d], w1p[d * 128], hs);
    }
    hp[tid] = hs;
    __syncthreads();

    if (tid < 128) {
        float x = hp[tid] + hp[tid + 128] + hp[tid + 256] + hp[tid + 384] + b1[tid];
        float g = 0.5f * x * (1.f + erff(x * 0.7071067811865476f));
        hp[tid] = g * w2[tid];
    }
    __syncthreads();
    if (tid < 32) {
        float r = hp[tid] + hp[tid + 32] + hp[tid + 64] + hp[tid + 96];
        #pragma unroll
        for (int o = 16; o; o >>= 1) r += __shfl_xor_sync(0xffffffffu, r, o);
        if (tid == 0) g_gate[bc] = 1.f / (1.f + __expf(-(r + b2[0])));
    }
}

// ---------------------------------------------------------------------------
// Gather attention. CTA per (b, h, n-half): 256 threads = 64 rows x 4 E-quads.
// Mask compaction fused in (warp ballot). K/V rows loaded directly from gmem
// (L1 catches ~7x reuse); no barriers in the mainloop.
// ---------------------------------------------------------------------------
__global__ __launch_bounds__(256, 4) void attn_kernel(
        const float* __restrict__ q,
        const float* __restrict__ keys,
        const float* __restrict__ values,
        const unsigned char* __restrict__ mask,
        float* __restrict__ out) {
    __shared__ unsigned char jl[64 * CAP];
    __shared__ int jc[64];
    __shared__ int ok8;

    const int b  = blockIdx.x >> 4;
    const int h  = (blockIdx.x >> 1) & 7;
    const int nh = blockIdx.x & 1;
    const int tid = threadIdx.x;
    const int w = tid >> 5;
    const int lane = tid & 31;

    // ---- mask dtype autodetect: diagonal of this head is always true ----
    if (tid == 0) ok8 = 1;
    __syncthreads();
    if (tid < 64) {
        int row = nh * 64 + tid;
        if (mask[(size_t)(h * Ndim + row) * Ndim + row] == 0) atomicExch(&ok8, 0);
    }
    __syncthreads();
    const bool byte_mode = (ok8 != 0);

    // ---- compact j-lists: warp w handles rows w*8 .. w*8+7 (local) ----
    #pragma unroll
    for (int r = 0; r < 8; r++) {
        int row_l = w * 8 + r;
        int row = nh * 64 + row_l;
        int lc = 0;
        unsigned char lj[4];
        if (byte_mode) {
            uchar4 v = ((const uchar4*)(mask + (size_t)(h * Ndim + row) * Ndim))[lane];
            if (v.x) lj[lc++] = (unsigned char)(lane * 4 + 0);
            if (v.y) lj[lc++] = (unsigned char)(lane * 4 + 1);
            if (v.z) lj[lc++] = (unsigned char)(lane * 4 + 2);
            if (v.w) lj[lc++] = (unsigned char)(lane * 4 + 3);
        } else {
            const unsigned int* m32 = (const unsigned int*)mask;
            uint4 v = ((const uint4*)(m32 + (size_t)(h * Ndim + row) * Ndim))[lane];
            if (v.x) lj[lc++] = (unsigned char)(lane * 4 + 0);
            if (v.y) lj[lc++] = (unsigned char)(lane * 4 + 1);
            if (v.z) lj[lc++] = (unsigned char)(lane * 4 + 2);
            if (v.w) lj[lc++] = (unsigned char)(lane * 4 + 3);
        }
        // warp inclusive scan of lc
        int off = lc;
        #pragma unroll
        for (int o = 1; o < 32; o <<= 1) {
            int t = __shfl_up_sync(0xffffffffu, off, o);
            if (lane >= o) off += t;
        }
        int excl = off - lc;
        for (int i = 0; i < lc; i++) jl[row_l * CAP + excl + i] = lj[i];
        if (lane == 31) jc[row_l] = off;  // total count (<=128)
    }
    __syncthreads();

    // ---- attention: 4 lanes per row, each owns 16 floats of E ----
    const int n_l = tid >> 2;           // local row 0..63
    const int ql  = tid & 3;            // quad lane
    const int n   = nh * 64 + n_l;
    const unsigned pm = 0xFu << (tid & 28);
    const int cnt = jc[n_l];
    const unsigned char* jrow = &jl[n_l * CAP];

    float4 q4[4];
    {
        const float4* qp = (const float4*)(q + (((size_t)b * Ndim + n) * Hdim + h) * Edim + ql * 16);
        #pragma unroll
        for (int t = 0; t < 4; t++) q4[t] = qp[t];
    }

    float4 acc[4];
    #pragma unroll
    for (int t = 0; t < 4; t++) acc[t] = make_float4(0.f, 0.f, 0.f, 0.f);
    float mrun = -INFINITY;
    float lrun = 0.f;

    for (int c = 0; c < Cdim; c++) {
        const float gc = g_gate[b * Cdim + c];
        const float* kb = keys   + ((size_t)(b * Cdim + c) * Ndim) * Ddim + h * Edim + ql * 16;
        const float* vb = values + ((size_t)(b * Cdim + c) * Ndim) * Ddim + h * Edim + ql * 16;

        for (int basei = 0; basei < cnt; basei += 8) {
            const int nch = min(8, cnt - basei);
            float lg[8];
            int js[8];
            float tmax = -INFINITY;
            for (int i = 0; i < nch; i++) {
                int j = jrow[basei + i];
                js[i] = j;
                const float4* kk = (const float4*)(kb + (size_t)j * Ddim);
                float d = 0.f;
                #pragma unroll
                for (int t = 0; t < 4; t++) {
                    float4 kv = kk[t];
                    d = fmaf(q4[t].x, kv.x, d);
                    d = fmaf(q4[t].y, kv.y, d);
                    d = fmaf(q4[t].z, kv.z, d);
                    d = fmaf(q4[t].w, kv.w, d);
                }
                d += __shfl_xor_sync(pm, d, 1);   // combine quad partials
                d += __shfl_xor_sync(pm, d, 2);
                lg[i] = d * 0.125f;               // scale = E^-0.5
                tmax = fmaxf(tmax, lg[i]);
            }
            float mnew = fmaxf(mrun, tmax);
            if (mnew > mrun) {
                float so = __expf(mrun - mnew);   // exp(-inf)=0 first chunk
                lrun *= so;
                #pragma unroll
                for (int t = 0; t < 4; t++) {
                    acc[t].x *= so; acc[t].y *= so; acc[t].z *= so; acc[t].w *= so;
                }
                mrun = mnew;
            }
            for (int i = 0; i < nch; i++) {
                float p = __expf(lg[i] - mrun);
                lrun += p;                         // denominator excludes gate
                float pg = p * gc;                 // gate folded into PV
                const float4* vv4 = (const float4*)(vb + (size_t)js[i] * Ddim);
                #pragma unroll
                for (int t = 0; t < 4; t++) {
                    float4 vv = vv4[t];
                    acc[t].x = fmaf(pg, vv.x, acc[t].x);
                    acc[t].y = fmaf(pg, vv.y, acc[t].y);
                    acc[t].z = fmaf(pg, vv.z, acc[t].z);
                    acc[t].w = fmaf(pg, vv.w, acc[t].w);
                }
            }
        }
    }

    const float inv = (lrun > 0.f) ? (1.f / lrun) : 0.f;
    float4* op = (float4*)(out + (((size_t)b * Ndim + n) * Hdim + h) * Edim + ql * 16);
    #pragma unroll
    for (int t = 0; t < 4; t++) {
        float4 a = acc[t];
        a.x *= inv; a.y *= inv; a.z *= inv; a.w *= inv;
        op[t] = a;
    }
}

// ---------------------------------------------------------------------------
extern "C" void kernel_launch(void* const* d_in, const int* in_sizes, int n_in,
                              void* d_out, int out_size) {
    // Resolve inputs by element count, falling back to metadata order.
    int qi = 0, ki = 1, vi = 2, w1i = 3, b1i = 4, w2i = 5, b2i = 6, mi = 7;
    {
        int qx = -1, k1st = -1, k2nd = -1, w1x = -1, p1st = -1, p2nd = -1, bx = -1, mx = -1;
        for (int i = 0; i < n_in; i++) {
            int s = in_sizes[i];
            if (s == Bdim * Ndim * Hdim * Edim) qx = i;                 // 2097152
            else if (s == Bdim * Cdim * Ndim * Hdim * Edim) {           // 33554432
                if (k1st < 0) k1st = i; else k2nd = i;
            }
            else if (s == Ddim * (Ddim / 4)) w1x = i;                   // 65536
            else if (s == Ddim / 4) { if (p1st < 0) p1st = i; else p2nd = i; }
            else if (s == 1) bx = i;
            else if (s == Hdim * Ndim * Ndim) mx = i;                   // 131072
        }
        if (qx >= 0 && k1st >= 0 && k2nd >= 0 && w1x >= 0 && p1st >= 0 &&
            p2nd >= 0 && bx >= 0 && mx >= 0) {
            qi = qx; ki = k1st; vi = k2nd; w1i = w1x; b1i = p1st; w2i = p2nd;
            b2i = bx; mi = mx;
        }
    }

    const float* queries = (const float*)d_in[qi];
    const float* keys    = (const float*)d_in[ki];
    const float* values  = (const float*)d_in[vi];
    const float* w1      = (const float*)d_in[w1i];
    const float* b1      = (const float*)d_in[b1i];
    const float* w2      = (const float*)d_in[w2i];
    const float* b2      = (const float*)d_in[b2i];
    const unsigned char* na_mask = (const unsigned char*)d_in[mi];
    float* out = (float*)d_out;

    gate_kernel<<<Bdim * Cdim, 512>>>(values, w1, b1, w2, b2);
    attn_kernel<<<Bdim * Hdim * 2, 256>>>(queries, keys, values, na_mask, out);
}